// round 3
// baseline (speedup 1.0000x reference)
#include <cuda_runtime.h>

#define TDIM   8
#define NTOK   8192      // B*S = 4*2048
#define DLAT   1024
#define DSYM   256
#define NCODE  512

// ---------------- scratch (static device globals; no runtime allocation) ----
static __device__ int   g_top[NTOK];
static __device__ int   g_used[TDIM];
static __device__ float g_zread[NTOK * DLAT];     // 32 MB
static __device__ float g_raw[NTOK * DSYM];       //  8 MB
static __device__ float g_scores[NTOK * NCODE];   // 16 MB
static __device__ float g_h[NTOK * DLAT];         // 32 MB
static __device__ float g_cbn[NCODE];

// ---------------- small kernels --------------------------------------------
__global__ void k_init_used() {
    if (threadIdx.x < TDIM) g_used[threadIdx.x] = 0;
}

// one warp per token: relevance[t] = dot(syms[t][n], Wq); argmax over t
__global__ void k_topidx(const float* __restrict__ syms,
                         const float* __restrict__ Wq) {
    int warp = (blockIdx.x * blockDim.x + threadIdx.x) >> 5;
    int lane = threadIdx.x & 31;
    if (warp >= NTOK) return;
    float wq[8];
#pragma unroll
    for (int i = 0; i < 8; i++) wq[i] = Wq[lane + 32 * i];
    float best = -3.0e38f;
    int bt = 0;
    for (int t = 0; t < TDIM; t++) {
        const float* row = syms + ((size_t)t * NTOK + warp) * DSYM;
        float s = 0.f;
#pragma unroll
        for (int i = 0; i < 8; i++) s += row[lane + 32 * i] * wq[i];
#pragma unroll
        for (int o = 16; o; o >>= 1) s += __shfl_xor_sync(0xffffffffu, s, o);
        if (s > best) { best = s; bt = t; }   // strict >  => first max (JAX argmax)
    }
    if (lane == 0) {
        g_top[warp] = bt;
        g_used[bt] = 1;                       // all writers store 1; race benign
    }
}

__global__ void k_cbnorm(const float* __restrict__ cb) {
    int c = blockIdx.x * blockDim.x + threadIdx.x;
    if (c < NCODE) {
        float s = 0.f;
        const float* row = cb + (size_t)c * DSYM;
#pragma unroll 8
        for (int k = 0; k < DSYM; k++) { float v = row[k]; s += v * v; }
        g_cbn[c] = s;
    }
}

// one warp per token: argmin_c (||cb_c||^2 - 2*dot)  + gather quantized row
__global__ void k_vq(const float* __restrict__ cb,
                     float* __restrict__ quant_out,
                     float* __restrict__ idx_out) {
    int warp = (blockIdx.x * blockDim.x + threadIdx.x) >> 5;
    int lane = threadIdx.x & 31;
    if (warp >= NTOK) return;
    const float* srow = g_scores + (size_t)warp * NCODE;
    float best = 3.0e38f;
    int bi = 0x7fffffff;
    for (int c = lane; c < NCODE; c += 32) {
        float d = g_cbn[c] - 2.f * srow[c];
        if (d < best) { best = d; bi = c; }   // ascending scan keeps lowest idx
    }
#pragma unroll
    for (int o = 16; o; o >>= 1) {
        float ov = __shfl_xor_sync(0xffffffffu, best, o);
        int   oi = __shfl_xor_sync(0xffffffffu, bi, o);
        if (ov < best || (ov == best && oi < bi)) { best = ov; bi = oi; }
    }
    // bi identical across warp
    const float4* q = (const float4*)(cb + (size_t)bi * DSYM);
    float4* dst = (float4*)(quant_out + (size_t)warp * DSYM);
#pragma unroll
    for (int i = lane; i < DSYM / 4; i += 32) dst[i] = q[i];
    if (lane == 0) idx_out[warp] = (float)bi;
}

__global__ void k_mask(float* __restrict__ mask_out) {
    int t = threadIdx.x;
    if (t < TDIM) mask_out[t] = (g_used[t] == 0) ? 1.f : 0.f;
}

// ---------------- tiled fp32 SGEMM (double-buffered, TM=16 x TN=8) ----------
// 128 threads per 128x128 tile; per-thread 16x8 outputs.
// C[M,N] = A[M,K] @ B[K,N] (+bias) (relu?) (+res)
// AMODE 0: A0 row-major [M,K]
// AMODE 1: "zcat+gather": k<split -> A0[m, k] (ld=split)
//                         else    -> A1[(top[m]*NTOK + m)*(K-split) + (k-split)]
// AMODE 2: "hcat": k<split -> A0[m,k] (ld=split); else A1[m, k-split] (ld=K-split)
// BMODE 0: B row-major [K,N];  BMODE 1: B is [N,K], element(k,n)=B[n*K+k]
#define BM 128
#define BN 128
#define BK 16
#define TM 16
#define TN 8
#define NTHR 128

template <int AMODE, int BMODE>
__global__ __launch_bounds__(NTHR, 2)
void k_sgemm(const float* __restrict__ A0, const float* __restrict__ A1,
             const int* __restrict__ top,
             const float* __restrict__ B,
             const float* __restrict__ bias,
             const float* __restrict__ res,
             int relu,
             float* __restrict__ C,
             int M, int N, int K, int split)
{
    __shared__ float As[2][BK][BM + 4];
    __shared__ float Bs[2][BK][BN + 4];
    const int bm = blockIdx.y * BM;
    const int bn = blockIdx.x * BN;
    const int tid = threadIdx.x;
    const int tx = tid & 15;       // n dir: tx*TN covers 128
    const int ty = tid >> 4;       // m dir: ty*TM covers 128

    // per-thread A load coords: 512 float4 loads / 128 threads = 4 each
    const float* a0base[4];
    const float* a1base[4];
    int arow[4], akc[4];
#pragma unroll
    for (int l = 0; l < 4; l++) {
        int c = tid + l * NTHR;
        arow[l] = c >> 2;                 // 0..127
        akc[l]  = (c & 3) * 4;            // 0,4,8,12
        int gm = bm + arow[l];
        if (AMODE == 0) {
            a0base[l] = A0 + (size_t)gm * K;
            a1base[l] = nullptr;
        } else if (AMODE == 1) {
            a0base[l] = A0 + (size_t)gm * split;
            a1base[l] = A1 + ((size_t)top[gm] * NTOK + gm) * (size_t)(K - split);
        } else {
            a0base[l] = A0 + (size_t)gm * split;
            a1base[l] = A1 + (size_t)gm * (K - split);
        }
    }

    float4 pa[4], pb[4];

    auto load_tile = [&](int kt) {
#pragma unroll
        for (int l = 0; l < 4; l++) {
            int gk = kt + akc[l];
            const float* src;
            if (AMODE == 0) src = a0base[l] + gk;
            else src = (gk < split) ? (a0base[l] + gk) : (a1base[l] + (gk - split));
            pa[l] = *(const float4*)src;
        }
#pragma unroll
        for (int l = 0; l < 4; l++) {
            int c = tid + l * NTHR;
            if (BMODE == 0) {
                int row = c >> 5;          // 0..15 (k within tile)
                int nc = (c & 31) * 4;
                pb[l] = *(const float4*)(B + (size_t)(kt + row) * N + bn + nc);
            } else {
                int n = c >> 2;            // 0..127
                int kc = (c & 3) * 4;
                pb[l] = *(const float4*)(B + (size_t)(bn + n) * K + kt + kc);
            }
        }
    };
    auto store_tile = [&](int buf) {
#pragma unroll
        for (int l = 0; l < 4; l++) {
            int row = arow[l], kc = akc[l];
            As[buf][kc + 0][row] = pa[l].x;
            As[buf][kc + 1][row] = pa[l].y;
            As[buf][kc + 2][row] = pa[l].z;
            As[buf][kc + 3][row] = pa[l].w;
        }
#pragma unroll
        for (int l = 0; l < 4; l++) {
            int c = tid + l * NTHR;
            if (BMODE == 0) {
                int row = c >> 5;
                int nc = (c & 31) * 4;
                *(float4*)&Bs[buf][row][nc] = pb[l];
            } else {
                int n = c >> 2;
                int kc = (c & 3) * 4;
                Bs[buf][kc + 0][n] = pb[l].x;
                Bs[buf][kc + 1][n] = pb[l].y;
                Bs[buf][kc + 2][n] = pb[l].z;
                Bs[buf][kc + 3][n] = pb[l].w;
            }
        }
    };

    float acc[TM][TN] = {};
    const int ktiles = K / BK;
    int buf = 0;

    load_tile(0);
    store_tile(0);
    __syncthreads();

    for (int t = 0; t < ktiles; t++) {
        const bool more = (t + 1 < ktiles);
        if (more) load_tile((t + 1) * BK);

#pragma unroll
        for (int k = 0; k < BK; k++) {
            float a[TM], b[TN];
#pragma unroll
            for (int q = 0; q < TM / 4; q++) {
                float4 v = *(const float4*)&As[buf][k][ty * TM + q * 4];
                a[q * 4 + 0] = v.x; a[q * 4 + 1] = v.y;
                a[q * 4 + 2] = v.z; a[q * 4 + 3] = v.w;
            }
#pragma unroll
            for (int q = 0; q < TN / 4; q++) {
                float4 v = *(const float4*)&Bs[buf][k][tx * TN + q * 4];
                b[q * 4 + 0] = v.x; b[q * 4 + 1] = v.y;
                b[q * 4 + 2] = v.z; b[q * 4 + 3] = v.w;
            }
#pragma unroll
            for (int i = 0; i < TM; i++)
#pragma unroll
                for (int j = 0; j < TN; j++)
                    acc[i][j] += a[i] * b[j];
        }

        if (more) {
            store_tile(buf ^ 1);
            __syncthreads();
            buf ^= 1;
        }
    }

    // ---- epilogue (vectorized) ----
    float4 bv0, bv1;
    if (bias) {
        bv0 = *(const float4*)(bias + bn + tx * TN);
        bv1 = *(const float4*)(bias + bn + tx * TN + 4);
    } else {
        bv0 = make_float4(0.f, 0.f, 0.f, 0.f);
        bv1 = bv0;
    }
#pragma unroll
    for (int i = 0; i < TM; i++) {
        int gm = bm + ty * TM + i;
        size_t base = (size_t)gm * N + bn + tx * TN;
        float4 v0 = make_float4(acc[i][0] + bv0.x, acc[i][1] + bv0.y,
                                acc[i][2] + bv0.z, acc[i][3] + bv0.w);
        float4 v1 = make_float4(acc[i][4] + bv1.x, acc[i][5] + bv1.y,
                                acc[i][6] + bv1.z, acc[i][7] + bv1.w);
        if (relu) {
            v0.x = fmaxf(v0.x, 0.f); v0.y = fmaxf(v0.y, 0.f);
            v0.z = fmaxf(v0.z, 0.f); v0.w = fmaxf(v0.w, 0.f);
            v1.x = fmaxf(v1.x, 0.f); v1.y = fmaxf(v1.y, 0.f);
            v1.z = fmaxf(v1.z, 0.f); v1.w = fmaxf(v1.w, 0.f);
        }
        if (res) {
            float4 r0 = *(const float4*)(res + base);
            float4 r1 = *(const float4*)(res + base + 4);
            v0.x += r0.x; v0.y += r0.y; v0.z += r0.z; v0.w += r0.w;
            v1.x += r1.x; v1.y += r1.y; v1.z += r1.z; v1.w += r1.w;
        }
        *(float4*)(C + base)     = v0;
        *(float4*)(C + base + 4) = v1;
    }
}

// ---------------- launch ----------------------------------------------------
extern "C" void kernel_launch(void* const* d_in, const int* in_sizes, int n_in,
                              void* d_out, int out_size)
{
    const float* token = (const float*)d_in[0];
    const float* syms  = (const float*)d_in[1];
    const float* outs  = (const float*)d_in[3];
    const float* Wq    = (const float*)d_in[5];
    const float* Wread = (const float*)d_in[7];
    const float* bread = (const float*)d_in[8];
    const float* Wsym  = (const float*)d_in[9];
    const float* bsym  = (const float*)d_in[10];
    const float* Wc1   = (const float*)d_in[11];
    const float* bc1   = (const float*)d_in[12];
    const float* Wc2   = (const float*)d_in[13];
    const float* bc2   = (const float*)d_in[14];
    const float* cb    = (const float*)d_in[15];

    float* out        = (float*)d_out;
    float* out_node   = out;                                  // 8192*1024
    float* out_quant  = out + (size_t)NTOK * DLAT;            // 8192*256
    float* out_idx    = out_quant + (size_t)NTOK * DSYM;      // 8192
    float* out_mask   = out_idx + NTOK;                       // 8

    void *p_top, *p_zread, *p_raw, *p_scores, *p_h;
    cudaGetSymbolAddress(&p_top,    g_top);
    cudaGetSymbolAddress(&p_zread,  g_zread);
    cudaGetSymbolAddress(&p_raw,    g_raw);
    cudaGetSymbolAddress(&p_scores, g_scores);
    cudaGetSymbolAddress(&p_h,      g_h);
    int*   top    = (int*)p_top;
    float* zread  = (float*)p_zread;
    float* raw    = (float*)p_raw;
    float* scores = (float*)p_scores;
    float* h      = (float*)p_h;

    k_init_used<<<1, 32>>>();
    k_topidx<<<(NTOK * 32 + 255) / 256, 256>>>(syms, Wq);
    k_cbnorm<<<2, 256>>>(cb);

    // z_read = [token | gathered_bus] @ Wread + bread    (M=8192,K=2048,N=1024)
    {
        dim3 grid(DLAT / BN, NTOK / BM);
        k_sgemm<1, 0><<<grid, NTHR>>>(token, outs, top, Wread, bread, nullptr, 0,
                                      zread, NTOK, DLAT, 2 * DLAT, DLAT);
    }
    // raw_symbol = z_read @ Wsym + bsym                  (K=1024,N=256)
    {
        dim3 grid(DSYM / BN, NTOK / BM);
        k_sgemm<0, 0><<<grid, NTHR>>>(zread, nullptr, nullptr, Wsym, bsym, nullptr, 0,
                                      raw, NTOK, DSYM, DLAT, 0);
    }
    // scores = raw @ codebook^T                          (K=256,N=512, B transposed)
    {
        dim3 grid(NCODE / BN, NTOK / BM);
        k_sgemm<0, 1><<<grid, NTHR>>>(raw, nullptr, nullptr, cb, nullptr, nullptr, 0,
                                      scores, NTOK, NCODE, DSYM, 0);
    }
    // VQ argmin + quantized gather + indices
    k_vq<<<(NTOK * 32 + 255) / 256, 256>>>(cb, out_quant, out_idx);

    // h = relu([z_read | quantized] @ Wc1 + bc1)         (K=1280,N=1024)
    {
        dim3 grid(DLAT / BN, NTOK / BM);
        k_sgemm<2, 0><<<grid, NTHR>>>(zread, out_quant, nullptr, Wc1, bc1, nullptr, 1,
                                      h, NTOK, DLAT, DLAT + DSYM, DLAT);
    }
    // node_output = h @ Wc2 + bc2 + token_state          (K=1024,N=1024)
    {
        dim3 grid(DLAT / BN, NTOK / BM);
        k_sgemm<0, 0><<<grid, NTHR>>>(h, nullptr, nullptr, Wc2, bc2, token, 0,
                                      out_node, NTOK, DLAT, DLAT, 0);
    }
    k_mask<<<1, 32>>>(out_mask);
}

// round 5
// speedup vs baseline: 1.3042x; 1.3042x over previous
#include <cuda_runtime.h>
#include <cuda_fp16.h>
#include <cstdint>

#define TDIM   8
#define NTOK   8192      // B*S = 4*2048
#define DLAT   1024
#define DSYM   256
#define NCODE  512

// ---------------- scratch (static device globals; no runtime allocation) ----
static __device__ int   g_top[NTOK];
static __device__ int   g_used[TDIM];
static __device__ float g_zread[NTOK * DLAT];
static __device__ float g_raw[NTOK * DSYM];
static __device__ float g_scores[NTOK * NCODE];
static __device__ float g_h[NTOK * DLAT];
static __device__ float g_cbn[NCODE];

// ---------------- small kernels --------------------------------------------
__global__ void k_init_used() {
    if (threadIdx.x < TDIM) g_used[threadIdx.x] = 0;
}

__global__ void k_topidx(const float* __restrict__ syms,
                         const float* __restrict__ Wq) {
    int warp = (blockIdx.x * blockDim.x + threadIdx.x) >> 5;
    int lane = threadIdx.x & 31;
    if (warp >= NTOK) return;
    float wq[8];
#pragma unroll
    for (int i = 0; i < 8; i++) wq[i] = Wq[lane + 32 * i];
    float best = -3.0e38f;
    int bt = 0;
    for (int t = 0; t < TDIM; t++) {
        const float* row = syms + ((size_t)t * NTOK + warp) * DSYM;
        float s = 0.f;
#pragma unroll
        for (int i = 0; i < 8; i++) s += row[lane + 32 * i] * wq[i];
#pragma unroll
        for (int o = 16; o; o >>= 1) s += __shfl_xor_sync(0xffffffffu, s, o);
        if (s > best) { best = s; bt = t; }
    }
    if (lane == 0) {
        g_top[warp] = bt;
        g_used[bt] = 1;
    }
}

__global__ void k_cbnorm(const float* __restrict__ cb) {
    int c = blockIdx.x * blockDim.x + threadIdx.x;
    if (c < NCODE) {
        float s = 0.f;
        const float* row = cb + (size_t)c * DSYM;
#pragma unroll 8
        for (int k = 0; k < DSYM; k++) { float v = row[k]; s += v * v; }
        g_cbn[c] = s;
    }
}

__global__ void k_vq(const float* __restrict__ cb,
                     float* __restrict__ quant_out,
                     float* __restrict__ idx_out) {
    int warp = (blockIdx.x * blockDim.x + threadIdx.x) >> 5;
    int lane = threadIdx.x & 31;
    if (warp >= NTOK) return;
    const float* srow = g_scores + (size_t)warp * NCODE;
    float best = 3.0e38f;
    int bi = 0x7fffffff;
    for (int c = lane; c < NCODE; c += 32) {
        float d = g_cbn[c] - 2.f * srow[c];
        if (d < best) { best = d; bi = c; }
    }
#pragma unroll
    for (int o = 16; o; o >>= 1) {
        float ov = __shfl_xor_sync(0xffffffffu, best, o);
        int   oi = __shfl_xor_sync(0xffffffffu, bi, o);
        if (ov < best || (ov == best && oi < bi)) { best = ov; bi = oi; }
    }
    const float4* q = (const float4*)(cb + (size_t)bi * DSYM);
    float4* dst = (float4*)(quant_out + (size_t)warp * DSYM);
#pragma unroll
    for (int i = lane; i < DSYM / 4; i += 32) dst[i] = q[i];
    if (lane == 0) idx_out[warp] = (float)bi;
}

__global__ void k_mask(float* __restrict__ mask_out) {
    int t = threadIdx.x;
    if (t < TDIM) mask_out[t] = (g_used[t] == 0) ? 1.f : 0.f;
}

// ---------------- fp16 split-precision tensor GEMM (mma.sync) ---------------
// C[M,N] = A[M,K] @ B[K,N] (+bias)(relu?)(+res), fp32 in/out.
// x = hi + lo (hi = fp16(x), lo = fp16(x-hi)); D = Ah*Bh + Ah*Bl + Al*Bh.
// CTA 128x128, BK=32, 8 warps (2x4), warp tile 64x32, double-buffered smem.
// AMODE 0: A0 row-major [M,K]
// AMODE 1: k<split -> A0[m,k](ld=split); else A1[(top[m]*NTOK+m)*(K-split)+(k-split)]
// AMODE 2: k<split -> A0[m,k](ld=split); else A1[m,k-split](ld=K-split)
// BMODE 0: B row-major [K,N];  BMODE 1: B is [N,K]
#define HS    36                 // halves per smem row (pad: conflict-free frags)
#define AOFF  (128 * HS)         // 4608 halves per matrix
#define BUFH  (4 * AOFF)         // Ah,Al,Bh,Bl per buffer
#define HG_SMEM (2 * BUFH * 2)   // bytes: 73728

#define MMA16816(d, a, b)                                             \
    asm volatile(                                                     \
        "mma.sync.aligned.m16n8k16.row.col.f32.f16.f16.f32 "          \
        "{%0,%1,%2,%3},{%4,%5,%6,%7},{%8,%9},{%0,%1,%2,%3};"          \
        : "+f"(d[0]), "+f"(d[1]), "+f"(d[2]), "+f"(d[3])              \
        : "r"(a[0]), "r"(a[1]), "r"(a[2]), "r"(a[3]),                 \
          "r"(b[0]), "r"(b[1]))

template <int AMODE, int BMODE>
__global__ __launch_bounds__(256, 1)
void k_hgemm(const float* __restrict__ A0, const float* __restrict__ A1,
             const int* __restrict__ top,
             const float* __restrict__ B,
             const float* __restrict__ bias,
             const float* __restrict__ res,
             int relu,
             float* __restrict__ C,
             int M, int N, int K, int split)
{
    extern __shared__ __half sh[];
    const int tid = threadIdx.x;
    const int wid = tid >> 5, lane = tid & 31;
    const int wm = wid & 1, wn = wid >> 1;       // warp grid 2(m) x 4(n)
    const int g = lane >> 2, t4 = lane & 3;
    const int bm = blockIdx.y * 128, bn = blockIdx.x * 128;

    // per-thread A source bases (4 float4 loads per tile; row=c>>3, kc=(c&7)*4)
    const float* a0base[4];
    const float* a1base[4];
    int akc[4];
#pragma unroll
    for (int l = 0; l < 4; l++) {
        int c = tid + l * 256;
        int row = c >> 3;
        akc[l] = (c & 7) * 4;
        int gm = bm + row;
        if (AMODE == 0) {
            a0base[l] = A0 + (size_t)gm * K;
            a1base[l] = nullptr;
        } else if (AMODE == 1) {
            a0base[l] = A0 + (size_t)gm * split;
            a1base[l] = A1 + ((size_t)top[gm] * NTOK + gm) * (size_t)(K - split);
        } else {
            a0base[l] = A0 + (size_t)gm * split;
            a1base[l] = A1 + (size_t)gm * (K - split);
        }
    }

    float4 pa[4], pb[4];

    auto load_tile = [&](int kt) {
#pragma unroll
        for (int l = 0; l < 4; l++) {
            int gk = kt + akc[l];
            const float* src;
            if (AMODE == 0) src = a0base[l] + gk;
            else src = (gk < split) ? (a0base[l] + gk) : (a1base[l] + (gk - split));
            pa[l] = *(const float4*)src;
        }
#pragma unroll
        for (int l = 0; l < 4; l++) {
            int c = tid + l * 256;
            if (BMODE == 0) {
                int kr = c >> 5;                // 0..31
                int nc = (c & 31) * 4;          // 0..124
                pb[l] = *(const float4*)(B + (size_t)(kt + kr) * N + bn + nc);
            } else {
                int nr = c >> 3;                // 0..127
                int kc = (c & 7) * 4;
                pb[l] = *(const float4*)(B + (size_t)(bn + nr) * K + kt + kc);
            }
        }
    };

    auto cvt_store4 = [&](__half* dst_hi, __half* dst_lo, float4 v) {
        __half hx = __float2half_rn(v.x), hy = __float2half_rn(v.y);
        __half hz = __float2half_rn(v.z), hw = __float2half_rn(v.w);
        __half lx = __float2half_rn(v.x - __half2float(hx));
        __half ly = __float2half_rn(v.y - __half2float(hy));
        __half lz = __float2half_rn(v.z - __half2float(hz));
        __half lw = __float2half_rn(v.w - __half2float(hw));
        *(__half2*)(dst_hi)     = __halves2half2(hx, hy);
        *(__half2*)(dst_hi + 2) = __halves2half2(hz, hw);
        *(__half2*)(dst_lo)     = __halves2half2(lx, ly);
        *(__half2*)(dst_lo + 2) = __halves2half2(lz, lw);
    };

    auto store_tile = [&](int buf) {
        __half* base = sh + buf * BUFH;
#pragma unroll
        for (int l = 0; l < 4; l++) {
            int c = tid + l * 256;
            int row = c >> 3;
            int kc = akc[l];
            int off = row * HS + kc;
            cvt_store4(base + off, base + AOFF + off, pa[l]);
        }
#pragma unroll
        for (int l = 0; l < 4; l++) {
            int c = tid + l * 256;
            if (BMODE == 0) {
                int kr = c >> 5;
                int nc = (c & 31) * 4;
                float v[4] = {pb[l].x, pb[l].y, pb[l].z, pb[l].w};
#pragma unroll
                for (int j = 0; j < 4; j++) {
                    __half h = __float2half_rn(v[j]);
                    __half lo = __float2half_rn(v[j] - __half2float(h));
                    base[2 * AOFF + (nc + j) * HS + kr] = h;
                    base[3 * AOFF + (nc + j) * HS + kr] = lo;
                }
            } else {
                int nr = c >> 3;
                int kc = (c & 7) * 4;
                int off = nr * HS + kc;
                cvt_store4(base + 2 * AOFF + off, base + 3 * AOFF + off, pb[l]);
            }
        }
    };

    float acc[4][4][4] = {};
    const int T = K / 32;
    int buf = 0;

    load_tile(0);
    store_tile(0);
    __syncthreads();

    for (int t = 0; t < T; t++) {
        const bool more = (t + 1 < T);
        if (more) load_tile((t + 1) * 32);

        const __half* Sa = sh + buf * BUFH;
        const __half* Sb = Sa + 2 * AOFF;
#pragma unroll
        for (int s = 0; s < 2; s++) {
            const int k0 = s * 16 + 2 * t4;
            uint32_t bh[4][2], bl[4][2];
#pragma unroll
            for (int j = 0; j < 4; j++) {
                int off = (wn * 32 + j * 8 + g) * HS + k0;
                bh[j][0] = *(const uint32_t*)(Sb + off);
                bh[j][1] = *(const uint32_t*)(Sb + off + 8);
                bl[j][0] = *(const uint32_t*)(Sb + AOFF + off);
                bl[j][1] = *(const uint32_t*)(Sb + AOFF + off + 8);
            }
#pragma unroll
            for (int i = 0; i < 4; i++) {
                int r0 = (wm * 64 + i * 16 + g) * HS + k0;
                int r1 = r0 + 8 * HS;
                uint32_t ah[4], al[4];
                ah[0] = *(const uint32_t*)(Sa + r0);
                ah[1] = *(const uint32_t*)(Sa + r1);
                ah[2] = *(const uint32_t*)(Sa + r0 + 8);
                ah[3] = *(const uint32_t*)(Sa + r1 + 8);
                al[0] = *(const uint32_t*)(Sa + AOFF + r0);
                al[1] = *(const uint32_t*)(Sa + AOFF + r1);
                al[2] = *(const uint32_t*)(Sa + AOFF + r0 + 8);
                al[3] = *(const uint32_t*)(Sa + AOFF + r1 + 8);
#pragma unroll
                for (int j = 0; j < 4; j++) {
                    MMA16816(acc[i][j], ah, bh[j]);
                    MMA16816(acc[i][j], ah, bl[j]);
                    MMA16816(acc[i][j], al, bh[j]);
                }
            }
        }

        if (more) {
            __syncthreads();          // ensure all warps done reading buf^1
            store_tile(buf ^ 1);
            __syncthreads();
            buf ^= 1;
        }
    }

    // ---- epilogue ----
#pragma unroll
    for (int i = 0; i < 4; i++) {
        int row0 = bm + wm * 64 + i * 16 + g;
#pragma unroll
        for (int j = 0; j < 4; j++) {
            int col = bn + wn * 32 + j * 8 + 2 * t4;
            float2 v0 = make_float2(acc[i][j][0], acc[i][j][1]);
            float2 v1 = make_float2(acc[i][j][2], acc[i][j][3]);
            if (bias) {
                float2 bv = *(const float2*)(bias + col);
                v0.x += bv.x; v0.y += bv.y;
                v1.x += bv.x; v1.y += bv.y;
            }
            if (relu) {
                v0.x = fmaxf(v0.x, 0.f); v0.y = fmaxf(v0.y, 0.f);
                v1.x = fmaxf(v1.x, 0.f); v1.y = fmaxf(v1.y, 0.f);
            }
            size_t o0 = (size_t)row0 * N + col;
            size_t o1 = (size_t)(row0 + 8) * N + col;
            if (res) {
                float2 r0 = *(const float2*)(res + o0);
                float2 r1 = *(const float2*)(res + o1);
                v0.x += r0.x; v0.y += r0.y;
                v1.x += r1.x; v1.y += r1.y;
            }
            *(float2*)(C + o0) = v0;
            *(float2*)(C + o1) = v1;
        }
    }
}

// ---------------- launch ----------------------------------------------------
extern "C" void kernel_launch(void* const* d_in, const int* in_sizes, int n_in,
                              void* d_out, int out_size)
{
    const float* token = (const float*)d_in[0];
    const float* syms  = (const float*)d_in[1];
    const float* outs  = (const float*)d_in[3];
    const float* Wq    = (const float*)d_in[5];
    const float* Wread = (const float*)d_in[7];
    const float* bread = (const float*)d_in[8];
    const float* Wsym  = (const float*)d_in[9];
    const float* bsym  = (const float*)d_in[10];
    const float* Wc1   = (const float*)d_in[11];
    const float* bc1   = (const float*)d_in[12];
    const float* Wc2   = (const float*)d_in[13];
    const float* bc2   = (const float*)d_in[14];
    const float* cb    = (const float*)d_in[15];

    float* out        = (float*)d_out;
    float* out_node   = out;
    float* out_quant  = out + (size_t)NTOK * DLAT;
    float* out_idx    = out_quant + (size_t)NTOK * DSYM;
    float* out_mask   = out_idx + NTOK;

    void *p_top, *p_zread, *p_raw, *p_scores, *p_h;
    cudaGetSymbolAddress(&p_top,    g_top);
    cudaGetSymbolAddress(&p_zread,  g_zread);
    cudaGetSymbolAddress(&p_raw,    g_raw);
    cudaGetSymbolAddress(&p_scores, g_scores);
    cudaGetSymbolAddress(&p_h,      g_h);
    int*   top    = (int*)p_top;
    float* zread  = (float*)p_zread;
    float* raw    = (float*)p_raw;
    float* scores = (float*)p_scores;
    float* h      = (float*)p_h;

    static int smem_set = 0;
    if (!smem_set) {
        cudaFuncSetAttribute(k_hgemm<1, 0>, cudaFuncAttributeMaxDynamicSharedMemorySize, HG_SMEM);
        cudaFuncSetAttribute(k_hgemm<0, 0>, cudaFuncAttributeMaxDynamicSharedMemorySize, HG_SMEM);
        cudaFuncSetAttribute(k_hgemm<0, 1>, cudaFuncAttributeMaxDynamicSharedMemorySize, HG_SMEM);
        cudaFuncSetAttribute(k_hgemm<2, 0>, cudaFuncAttributeMaxDynamicSharedMemorySize, HG_SMEM);
        smem_set = 1;
    }

    k_init_used<<<1, 32>>>();
    k_topidx<<<(NTOK * 32 + 255) / 256, 256>>>(syms, Wq);
    k_cbnorm<<<2, 256>>>(cb);

    // z_read = [token | gathered_bus] @ Wread + bread    (K=2048,N=1024)
    {
        dim3 grid(DLAT / 128, NTOK / 128);
        k_hgemm<1, 0><<<grid, 256, HG_SMEM>>>(token, outs, top, Wread, bread, nullptr, 0,
                                              zread, NTOK, DLAT, 2 * DLAT, DLAT);
    }
    // raw_symbol = z_read @ Wsym + bsym                  (K=1024,N=256)
    {
        dim3 grid(DSYM / 128, NTOK / 128);
        k_hgemm<0, 0><<<grid, 256, HG_SMEM>>>(zread, nullptr, nullptr, Wsym, bsym, nullptr, 0,
                                              raw, NTOK, DSYM, DLAT, 0);
    }
    // scores = raw @ codebook^T                          (K=256,N=512, B=[N,K])
    {
        dim3 grid(NCODE / 128, NTOK / 128);
        k_hgemm<0, 1><<<grid, 256, HG_SMEM>>>(raw, nullptr, nullptr, cb, nullptr, nullptr, 0,
                                              scores, NTOK, NCODE, DSYM, 0);
    }
    k_vq<<<(NTOK * 32 + 255) / 256, 256>>>(cb, out_quant, out_idx);

    // h = relu([z_read | quantized] @ Wc1 + bc1)         (K=1280,N=1024)
    {
        dim3 grid(DLAT / 128, NTOK / 128);
        k_hgemm<2, 0><<<grid, 256, HG_SMEM>>>(zread, out_quant, nullptr, Wc1, bc1, nullptr, 1,
                                              h, NTOK, DLAT, DLAT + DSYM, DLAT);
    }
    // node_output = h @ Wc2 + bc2 + token_state          (K=1024,N=1024)
    {
        dim3 grid(DLAT / 128, NTOK / 128);
        k_hgemm<0, 0><<<grid, 256, HG_SMEM>>>(h, nullptr, nullptr, Wc2, bc2, token, 0,
                                              out_node, NTOK, DLAT, DLAT, 0);
    }
    k_mask<<<1, 32>>>(out_mask);
}

// round 6
// speedup vs baseline: 2.3655x; 1.8138x over previous
#include <cuda_runtime.h>
#include <cuda_fp16.h>
#include <cstdint>

#define TDIM   8
#define NTOK   8192
#define DLAT   1024
#define DSYM   256
#define NCODE  512

// ---------------- scratch --------------------------------------------------
static __device__ int    g_top[NTOK];
static __device__ int    g_used[TDIM];
static __device__ float  g_scores[NTOK * NCODE];
static __device__ float  g_cbn[NCODE];
// half hi/lo buffers
static __device__ __half g_bcH[NTOK * 2 * DLAT],  g_bcL[NTOK * 2 * DLAT];     // [8192,2048]
static __device__ __half g_zcH[NTOK * (DLAT + DSYM)], g_zcL[NTOK * (DLAT + DSYM)]; // [8192,1280]
static __device__ __half g_rwH[NTOK * DSYM],      g_rwL[NTOK * DSYM];         // raw [8192,256]
static __device__ __half g_hH[NTOK * DLAT],       g_hL[NTOK * DLAT];          // h   [8192,1024]
static __device__ __half g_WreadH[DLAT * 2 * DLAT], g_WreadL[DLAT * 2 * DLAT];    // [1024,2048]
static __device__ __half g_WsymH[DSYM * DLAT],    g_WsymL[DSYM * DLAT];       // [256,1024]
static __device__ __half g_Wc1H[DLAT * (DLAT + DSYM)], g_Wc1L[DLAT * (DLAT + DSYM)]; // [1024,1280]
static __device__ __half g_Wc2H[DLAT * DLAT],     g_Wc2L[DLAT * DLAT];        // [1024,1024]
static __device__ __half g_cbH[NCODE * DSYM],     g_cbL[NCODE * DSYM];        // [512,256]

static __device__ __forceinline__ void split_h(float v, __half& h, __half& l) {
    h = __float2half_rn(v);
    l = __float2half_rn(v - __half2float(h));
}

// ---------------- small kernels --------------------------------------------
__global__ void k_init_used() {
    if (threadIdx.x < TDIM) g_used[threadIdx.x] = 0;
}

__global__ void k_topidx(const float* __restrict__ syms,
                         const float* __restrict__ Wq) {
    int warp = (blockIdx.x * blockDim.x + threadIdx.x) >> 5;
    int lane = threadIdx.x & 31;
    if (warp >= NTOK) return;
    float wq[8];
#pragma unroll
    for (int i = 0; i < 8; i++) wq[i] = Wq[lane + 32 * i];
    float best = -3.0e38f;
    int bt = 0;
    for (int t = 0; t < TDIM; t++) {
        const float* row = syms + ((size_t)t * NTOK + warp) * DSYM;
        float s = 0.f;
#pragma unroll
        for (int i = 0; i < 8; i++) s += row[lane + 32 * i] * wq[i];
#pragma unroll
        for (int o = 16; o; o >>= 1) s += __shfl_xor_sync(0xffffffffu, s, o);
        if (s > best) { best = s; bt = t; }
    }
    if (lane == 0) { g_top[warp] = bt; g_used[bt] = 1; }
}

__global__ void k_cbnorm(const float* __restrict__ cb) {
    int c = blockIdx.x * blockDim.x + threadIdx.x;
    if (c < NCODE) {
        float s = 0.f;
        const float* row = cb + (size_t)c * DSYM;
#pragma unroll 8
        for (int k = 0; k < DSYM; k++) { float v = row[k]; s += v * v; }
        g_cbn[c] = s;
    }
}

// transpose+convert: W[K,N] fp32 -> H/L [N,K] half
__global__ void k_cvt_wt(const float* __restrict__ W, __half* __restrict__ H,
                         __half* __restrict__ L, int K, int N) {
    __shared__ float t[32][33];
    int n0 = blockIdx.x * 32, k0 = blockIdx.y * 32;
    int tx = threadIdx.x, ty = threadIdx.y;    // (32, 8)
#pragma unroll
    for (int i = 0; i < 4; i++)
        t[ty + 8 * i][tx] = W[(size_t)(k0 + ty + 8 * i) * N + n0 + tx];
    __syncthreads();
#pragma unroll
    for (int i = 0; i < 4; i++) {
        float v = t[tx][ty + 8 * i];
        __half h, l; split_h(v, h, l);
        size_t o = (size_t)(n0 + ty + 8 * i) * K + k0 + tx;
        H[o] = h; L[o] = l;
    }
}

__global__ void k_cvt_cb(const float* __restrict__ cb) {
    int i = blockIdx.x * blockDim.x + threadIdx.x;
    if (i < NCODE * DSYM) {
        __half h, l; split_h(cb[i], h, l);
        g_cbH[i] = h; g_cbL[i] = l;
    }
}

// build [token | gathered bus] as half hi/lo [8192,2048]
__global__ void k_buscat(const float* __restrict__ token,
                         const float* __restrict__ outs) {
    int idx = blockIdx.x * blockDim.x + threadIdx.x;   // 8192*512
    int r = idx >> 9;
    int col = (idx & 511) * 4;
    const float* src;
    if (col < DLAT) src = token + (size_t)r * DLAT + col;
    else src = outs + ((size_t)g_top[r] * NTOK + r) * DLAT + (col - DLAT);
    float4 v = *(const float4*)src;
    __half h[4], l[4];
    split_h(v.x, h[0], l[0]); split_h(v.y, h[1], l[1]);
    split_h(v.z, h[2], l[2]); split_h(v.w, h[3], l[3]);
    size_t o = (size_t)r * 2048 + col;
    *(__half2*)(g_bcH + o)     = __halves2half2(h[0], h[1]);
    *(__half2*)(g_bcH + o + 2) = __halves2half2(h[2], h[3]);
    *(__half2*)(g_bcL + o)     = __halves2half2(l[0], l[1]);
    *(__half2*)(g_bcL + o + 2) = __halves2half2(l[2], l[3]);
}

// VQ argmin + gathers: fp32 quant out + halves into zc cols 1024..1279
__global__ void k_vq(const float* __restrict__ cb,
                     float* __restrict__ quant_out,
                     float* __restrict__ idx_out) {
    int warp = (blockIdx.x * blockDim.x + threadIdx.x) >> 5;
    int lane = threadIdx.x & 31;
    if (warp >= NTOK) return;
    const float* srow = g_scores + (size_t)warp * NCODE;
    float best = 3.0e38f;
    int bi = 0x7fffffff;
    for (int c = lane; c < NCODE; c += 32) {
        float d = g_cbn[c] - 2.f * srow[c];
        if (d < best) { best = d; bi = c; }
    }
#pragma unroll
    for (int o = 16; o; o >>= 1) {
        float ov = __shfl_xor_sync(0xffffffffu, best, o);
        int   oi = __shfl_xor_sync(0xffffffffu, bi, o);
        if (ov < best || (ov == best && oi < bi)) { best = ov; bi = oi; }
    }
    const float4* q = (const float4*)(cb + (size_t)bi * DSYM);
    float4* dst = (float4*)(quant_out + (size_t)warp * DSYM);
#pragma unroll
    for (int i = lane; i < DSYM / 4; i += 32) dst[i] = q[i];
    // halves into zc
    const float4* qh = (const float4*)(g_cbH + (size_t)bi * DSYM);  // 8 halves
    const float4* ql = (const float4*)(g_cbL + (size_t)bi * DSYM);
    float4* dH = (float4*)(g_zcH + (size_t)warp * 1280 + 1024);
    float4* dL = (float4*)(g_zcL + (size_t)warp * 1280 + 1024);
#pragma unroll
    for (int i = lane; i < DSYM / 8; i += 32) { dH[i] = qh[i]; dL[i] = ql[i]; }
    if (lane == 0) idx_out[warp] = (float)bi;
}

__global__ void k_mask(float* __restrict__ mask_out) {
    int t = threadIdx.x;
    if (t < TDIM) mask_out[t] = (g_used[t] == 0) ? 1.f : 0.f;
}

// ---------------- fp16 split tensor GEMM: cp.async + ldmatrix ---------------
// C[M,N] = (Ah+Al)[M,K] @ (Bh+Bl)^T  (B stored [N,K]); D = AhBh + AhBl + AlBh
// CTA 128x128, BK=32, 8 warps (2x4), warp tile 64x32, 3-stage cp.async.
#define STG_B 32768                   // bytes per stage (4 x 8KB)
#define TC_SMEM (3 * STG_B)           // 98304

#define MMA16816(d, a, b)                                             \
    asm volatile(                                                     \
        "mma.sync.aligned.m16n8k16.row.col.f32.f16.f16.f32 "          \
        "{%0,%1,%2,%3},{%4,%5,%6,%7},{%8,%9},{%0,%1,%2,%3};"          \
        : "+f"(d[0]), "+f"(d[1]), "+f"(d[2]), "+f"(d[3])              \
        : "r"(a[0]), "r"(a[1]), "r"(a[2]), "r"(a[3]),                 \
          "r"(b[0]), "r"(b[1]))

static __device__ __forceinline__ uint32_t smem_u32(const void* p) {
    uint32_t a;
    asm("{ .reg .u64 t; cvta.to.shared.u64 t, %1; cvt.u32.u64 %0, t; }"
        : "=r"(a) : "l"(p));
    return a;
}
static __device__ __forceinline__ void cp16(uint32_t dst, const void* src) {
    asm volatile("cp.async.ca.shared.global [%0], [%1], 16;"
                 :: "r"(dst), "l"(src) : "memory");
}
static __device__ __forceinline__ void ldm4(uint32_t& r0, uint32_t& r1,
                                            uint32_t& r2, uint32_t& r3, uint32_t a) {
    asm volatile("ldmatrix.sync.aligned.m8n8.x4.shared.b16 {%0,%1,%2,%3}, [%4];"
                 : "=r"(r0), "=r"(r1), "=r"(r2), "=r"(r3) : "r"(a));
}

__global__ __launch_bounds__(256, 1)
void k_tc(const __half* __restrict__ Ah, const __half* __restrict__ Al, int lda,
          const __half* __restrict__ Bh, const __half* __restrict__ Bl,
          const float* __restrict__ bias, const float* __restrict__ res, int relu,
          float* __restrict__ C, __half* __restrict__ Ch, __half* __restrict__ Cl,
          int ldch, int N, int K)
{
    extern __shared__ char sm[];
    const uint32_t sb = smem_u32(sm);
    const int tid = threadIdx.x;
    const int wid = tid >> 5, lane = tid & 31;
    const int wm = wid & 1, wn = wid >> 1;
    const int g = lane >> 2, t4 = lane & 3;
    const int bm = blockIdx.y * 128, bn = blockIdx.x * 128;

    // cp.async coords: 2 chunks per matrix per thread
    int cr[2], cc[2];
#pragma unroll
    for (int l = 0; l < 2; l++) {
        int c = tid + l * 256;
        cr[l] = c >> 2;            // row 0..127
        cc[l] = c & 3;             // chunk 0..3
    }

    auto issue_stage = [&](int t) {
        const int kt = t * 32;
        const uint32_t s0 = sb + (t % 3) * STG_B;
#pragma unroll
        for (int l = 0; l < 2; l++) {
            int r = cr[l], ch = cc[l];
            uint32_t d = s0 + r * 64 + ((ch ^ ((r >> 1) & 3)) << 4);
            size_t ga = (size_t)(bm + r) * lda + kt + ch * 8;
            cp16(d,          Ah + ga);
            cp16(d + 8192,   Al + ga);
            size_t gb = (size_t)(bn + r) * K + kt + ch * 8;
            cp16(d + 16384,  Bh + gb);
            cp16(d + 24576,  Bl + gb);
        }
        asm volatile("cp.async.commit_group;" ::: "memory");
    };

    // ldmatrix per-lane bases
    const int amb = (lane & 7) + 8 * ((lane >> 3) & 1);   // A row within 16
    const int akl = (lane >> 4) & 1;                       // A k-chunk bit
    const int swa = (amb >> 1) & 3;
    const int bnb = (lane & 7) + 8 * ((lane >> 4) & 1);   // B row within 16
    const int bkl = (lane >> 3) & 1;
    const int swb = (bnb >> 1) & 3;

    float acc[4][4][4] = {};
    const int T = K / 32;

    issue_stage(0);
    issue_stage(1);

    for (int t = 0; t < T; t++) {
        asm volatile("cp.async.wait_group 1;" ::: "memory");
        __syncthreads();
        if (t + 2 < T) issue_stage(t + 2);
        else asm volatile("cp.async.commit_group;" ::: "memory");

        const uint32_t s0 = sb + (t % 3) * STG_B;
        const uint32_t aH = s0, aL = s0 + 8192;
        const uint32_t bH = s0 + 16384, bL = s0 + 24576;
#pragma unroll
        for (int s = 0; s < 2; s++) {
            uint32_t bh[4][2], bl[4][2];
#pragma unroll
            for (int jp = 0; jp < 2; jp++) {
                uint32_t off = (uint32_t)(wn * 32 + jp * 16 + bnb) * 64
                             + (((s * 2 + bkl) ^ swb) << 4);
                ldm4(bh[2 * jp][0], bh[2 * jp][1], bh[2 * jp + 1][0], bh[2 * jp + 1][1],
                     bH + off);
                ldm4(bl[2 * jp][0], bl[2 * jp][1], bl[2 * jp + 1][0], bl[2 * jp + 1][1],
                     bL + off);
            }
#pragma unroll
            for (int i = 0; i < 4; i++) {
                uint32_t off = (uint32_t)(wm * 64 + i * 16 + amb) * 64
                             + (((s * 2 + akl) ^ swa) << 4);
                uint32_t ah[4], al[4];
                ldm4(ah[0], ah[1], ah[2], ah[3], aH + off);
                ldm4(al[0], al[1], al[2], al[3], aL + off);
#pragma unroll
                for (int j = 0; j < 4; j++) {
                    MMA16816(acc[i][j], ah, bh[j]);
                    MMA16816(acc[i][j], ah, bl[j]);
                    MMA16816(acc[i][j], al, bh[j]);
                }
            }
        }
    }

    // ---- epilogue ----
#pragma unroll
    for (int i = 0; i < 4; i++) {
        int row0 = bm + wm * 64 + i * 16 + g;
#pragma unroll
        for (int j = 0; j < 4; j++) {
            int col = bn + wn * 32 + j * 8 + 2 * t4;
            float2 v0 = make_float2(acc[i][j][0], acc[i][j][1]);
            float2 v1 = make_float2(acc[i][j][2], acc[i][j][3]);
            if (bias) {
                float2 bv = *(const float2*)(bias + col);
                v0.x += bv.x; v0.y += bv.y;
                v1.x += bv.x; v1.y += bv.y;
            }
            if (relu) {
                v0.x = fmaxf(v0.x, 0.f); v0.y = fmaxf(v0.y, 0.f);
                v1.x = fmaxf(v1.x, 0.f); v1.y = fmaxf(v1.y, 0.f);
            }
            size_t o0 = (size_t)row0 * N + col;
            size_t o1 = (size_t)(row0 + 8) * N + col;
            if (res) {
                float2 r0 = *(const float2*)(res + o0);
                float2 r1 = *(const float2*)(res + o1);
                v0.x += r0.x; v0.y += r0.y;
                v1.x += r1.x; v1.y += r1.y;
            }
            if (C) {
                *(float2*)(C + o0) = v0;
                *(float2*)(C + o1) = v1;
            }
            if (Ch) {
                __half h0, l0, h1, l1;
                size_t p0 = (size_t)row0 * ldch + col;
                size_t p1 = (size_t)(row0 + 8) * ldch + col;
                split_h(v0.x, h0, l0); split_h(v0.y, h1, l1);
                *(__half2*)(Ch + p0) = __halves2half2(h0, h1);
                *(__half2*)(Cl + p0) = __halves2half2(l0, l1);
                split_h(v1.x, h0, l0); split_h(v1.y, h1, l1);
                *(__half2*)(Ch + p1) = __halves2half2(h0, h1);
                *(__half2*)(Cl + p1) = __halves2half2(l0, l1);
            }
        }
    }
}

// ---------------- launch ----------------------------------------------------
extern "C" void kernel_launch(void* const* d_in, const int* in_sizes, int n_in,
                              void* d_out, int out_size)
{
    const float* token = (const float*)d_in[0];
    const float* syms  = (const float*)d_in[1];
    const float* outs  = (const float*)d_in[3];
    const float* Wq    = (const float*)d_in[5];
    const float* Wread = (const float*)d_in[7];
    const float* bread = (const float*)d_in[8];
    const float* Wsym  = (const float*)d_in[9];
    const float* bsym  = (const float*)d_in[10];
    const float* Wc1   = (const float*)d_in[11];
    const float* bc1   = (const float*)d_in[12];
    const float* Wc2   = (const float*)d_in[13];
    const float* bc2   = (const float*)d_in[14];
    const float* cb    = (const float*)d_in[15];

    float* out        = (float*)d_out;
    float* out_node   = out;
    float* out_quant  = out + (size_t)NTOK * DLAT;
    float* out_idx    = out_quant + (size_t)NTOK * DSYM;
    float* out_mask   = out_idx + NTOK;

#define SYM_PTR(T, sym) ([]{ void* p; cudaGetSymbolAddress(&p, sym); return (T*)p; }())
    float*  scores = SYM_PTR(float,  g_scores);
    __half* bcH = SYM_PTR(__half, g_bcH); __half* bcL = SYM_PTR(__half, g_bcL);
    __half* zcH = SYM_PTR(__half, g_zcH); __half* zcL = SYM_PTR(__half, g_zcL);
    __half* rwH = SYM_PTR(__half, g_rwH); __half* rwL = SYM_PTR(__half, g_rwL);
    __half* hH  = SYM_PTR(__half, g_hH);  __half* hL  = SYM_PTR(__half, g_hL);
    __half* WrH = SYM_PTR(__half, g_WreadH); __half* WrL = SYM_PTR(__half, g_WreadL);
    __half* WsH = SYM_PTR(__half, g_WsymH);  __half* WsL = SYM_PTR(__half, g_WsymL);
    __half* W1H = SYM_PTR(__half, g_Wc1H);   __half* W1L = SYM_PTR(__half, g_Wc1L);
    __half* W2H = SYM_PTR(__half, g_Wc2H);   __half* W2L = SYM_PTR(__half, g_Wc2L);
    __half* cbH = SYM_PTR(__half, g_cbH);    __half* cbL = SYM_PTR(__half, g_cbL);

    static int once = 0;
    if (!once) {
        cudaFuncSetAttribute(k_tc, cudaFuncAttributeMaxDynamicSharedMemorySize, TC_SMEM);
        once = 1;
    }

    k_init_used<<<1, 32>>>();
    k_topidx<<<(NTOK * 32 + 255) / 256, 256>>>(syms, Wq);
    k_cbnorm<<<2, 256>>>(cb);
    // weight converts (transpose to [N,K])
    { dim3 g(DLAT / 32, 2 * DLAT / 32);        k_cvt_wt<<<g, dim3(32, 8)>>>(Wread, WrH, WrL, 2 * DLAT, DLAT); }
    { dim3 g(DSYM / 32, DLAT / 32);            k_cvt_wt<<<g, dim3(32, 8)>>>(Wsym, WsH, WsL, DLAT, DSYM); }
    { dim3 g(DLAT / 32, (DLAT + DSYM) / 32);   k_cvt_wt<<<g, dim3(32, 8)>>>(Wc1, W1H, W1L, DLAT + DSYM, DLAT); }
    { dim3 g(DLAT / 32, DLAT / 32);            k_cvt_wt<<<g, dim3(32, 8)>>>(Wc2, W2H, W2L, DLAT, DLAT); }
    k_cvt_cb<<<(NCODE * DSYM + 255) / 256, 256>>>(cb);
    k_buscat<<<NTOK * 512 / 256, 256>>>(token, outs);

    // 1) zc[:,0:1024] = bc @ Wread^T + bread   (K=2048, N=1024) -> hi/lo only
    k_tc<<<dim3(DLAT / 128, NTOK / 128), 256, TC_SMEM>>>(
        bcH, bcL, 2 * DLAT, WrH, WrL, bread, nullptr, 0,
        nullptr, zcH, zcL, DLAT + DSYM, DLAT, 2 * DLAT);
    // 2) raw = zc[:,0:1024] @ Wsym^T + bsym    (K=1024, N=256) -> hi/lo
    k_tc<<<dim3(DSYM / 128, NTOK / 128), 256, TC_SMEM>>>(
        zcH, zcL, DLAT + DSYM, WsH, WsL, bsym, nullptr, 0,
        nullptr, rwH, rwL, DSYM, DSYM, DLAT);
    // 3) scores = raw @ cb^T                   (K=256, N=512) -> fp32
    k_tc<<<dim3(NCODE / 128, NTOK / 128), 256, TC_SMEM>>>(
        rwH, rwL, DSYM, cbH, cbL, nullptr, nullptr, 0,
        scores, nullptr, nullptr, 0, NCODE, DSYM);
    // VQ argmin + gathers (fills zc[:,1024:1280] halves)
    k_vq<<<(NTOK * 32 + 255) / 256, 256>>>(cb, out_quant, out_idx);
    // 4) h = relu(zc @ Wc1^T + bc1)            (K=1280, N=1024) -> hi/lo
    k_tc<<<dim3(DLAT / 128, NTOK / 128), 256, TC_SMEM>>>(
        zcH, zcL, DLAT + DSYM, W1H, W1L, bc1, nullptr, 1,
        nullptr, hH, hL, DLAT, DLAT, DLAT + DSYM);
    // 5) out = h @ Wc2^T + bc2 + token         (K=1024, N=1024) -> fp32
    k_tc<<<dim3(DLAT / 128, NTOK / 128), 256, TC_SMEM>>>(
        hH, hL, DLAT, W2H, W2L, bc2, token, 0,
        out_node, nullptr, nullptr, 0, DLAT, DLAT);
    k_mask<<<1, 32>>>(out_mask);
}

// round 7
// speedup vs baseline: 2.5875x; 1.0938x over previous
#include <cuda_runtime.h>
#include <cuda_fp16.h>
#include <cstdint>

#define TDIM   8
#define NTOK   8192
#define DLAT   1024
#define DSYM   256
#define NCODE  512

// ---------------- scratch --------------------------------------------------
static __device__ int    g_top[NTOK];
static __device__ int    g_used[TDIM];
static __device__ float  g_scores[NTOK * NCODE];
static __device__ float  g_cbn[NCODE];
// half hi/lo buffers
static __device__ __half g_bcH[NTOK * 2 * DLAT],  g_bcL[NTOK * 2 * DLAT];     // [8192,2048]
static __device__ __half g_zcH[NTOK * (DLAT + DSYM)], g_zcL[NTOK * (DLAT + DSYM)]; // [8192,1280]
static __device__ __half g_rwH[NTOK * DSYM],      g_rwL[NTOK * DSYM];         // raw [8192,256]
static __device__ __half g_hH[NTOK * DLAT],       g_hL[NTOK * DLAT];          // h   [8192,1024]
static __device__ __half g_WreadH[DLAT * 2 * DLAT], g_WreadL[DLAT * 2 * DLAT];
static __device__ __half g_WsymH[DSYM * DLAT],    g_WsymL[DSYM * DLAT];
static __device__ __half g_Wc1H[DLAT * (DLAT + DSYM)], g_Wc1L[DLAT * (DLAT + DSYM)];
static __device__ __half g_Wc2H[DLAT * DLAT],     g_Wc2L[DLAT * DLAT];
static __device__ __half g_cbH[NCODE * DSYM],     g_cbL[NCODE * DSYM];

static __device__ __forceinline__ void split_h(float v, __half& h, __half& l) {
    h = __float2half_rn(v);
    l = __float2half_rn(v - __half2float(h));
}

// ---------------- small kernels --------------------------------------------
__global__ void k_init_used() {
    if (threadIdx.x < TDIM) g_used[threadIdx.x] = 0;
}

__global__ void k_topidx(const float* __restrict__ syms,
                         const float* __restrict__ Wq) {
    int warp = (blockIdx.x * blockDim.x + threadIdx.x) >> 5;
    int lane = threadIdx.x & 31;
    if (warp >= NTOK) return;
    float wq[8];
#pragma unroll
    for (int i = 0; i < 8; i++) wq[i] = Wq[lane + 32 * i];
    float best = -3.0e38f;
    int bt = 0;
    for (int t = 0; t < TDIM; t++) {
        const float* row = syms + ((size_t)t * NTOK + warp) * DSYM;
        float s = 0.f;
#pragma unroll
        for (int i = 0; i < 8; i++) s += row[lane + 32 * i] * wq[i];
#pragma unroll
        for (int o = 16; o; o >>= 1) s += __shfl_xor_sync(0xffffffffu, s, o);
        if (s > best) { best = s; bt = t; }
    }
    if (lane == 0) { g_top[warp] = bt; g_used[bt] = 1; }
}

__global__ void k_cbnorm(const float* __restrict__ cb) {
    int c = blockIdx.x * blockDim.x + threadIdx.x;
    if (c < NCODE) {
        float s = 0.f;
        const float* row = cb + (size_t)c * DSYM;
#pragma unroll 8
        for (int k = 0; k < DSYM; k++) { float v = row[k]; s += v * v; }
        g_cbn[c] = s;
    }
}

// transpose+convert: W[K,N] fp32 -> H/L [N,K] half
__global__ void k_cvt_wt(const float* __restrict__ W, __half* __restrict__ H,
                         __half* __restrict__ L, int K, int N) {
    __shared__ float t[32][33];
    int n0 = blockIdx.x * 32, k0 = blockIdx.y * 32;
    int tx = threadIdx.x, ty = threadIdx.y;    // (32, 8)
#pragma unroll
    for (int i = 0; i < 4; i++)
        t[ty + 8 * i][tx] = W[(size_t)(k0 + ty + 8 * i) * N + n0 + tx];
    __syncthreads();
#pragma unroll
    for (int i = 0; i < 4; i++) {
        float v = t[tx][ty + 8 * i];
        __half h, l; split_h(v, h, l);
        size_t o = (size_t)(n0 + ty + 8 * i) * K + k0 + tx;
        H[o] = h; L[o] = l;
    }
}

__global__ void k_cvt_cb(const float* __restrict__ cb) {
    int i = blockIdx.x * blockDim.x + threadIdx.x;
    if (i < NCODE * DSYM) {
        __half h, l; split_h(cb[i], h, l);
        g_cbH[i] = h; g_cbL[i] = l;
    }
}

// build [token | gathered bus] as half hi/lo [8192,2048]
__global__ void k_buscat(const float* __restrict__ token,
                         const float* __restrict__ outs) {
    int idx = blockIdx.x * blockDim.x + threadIdx.x;   // 8192*512
    int r = idx >> 9;
    int col = (idx & 511) * 4;
    const float* src;
    if (col < DLAT) src = token + (size_t)r * DLAT + col;
    else src = outs + ((size_t)g_top[r] * NTOK + r) * DLAT + (col - DLAT);
    float4 v = *(const float4*)src;
    __half h[4], l[4];
    split_h(v.x, h[0], l[0]); split_h(v.y, h[1], l[1]);
    split_h(v.z, h[2], l[2]); split_h(v.w, h[3], l[3]);
    size_t o = (size_t)r * 2048 + col;
    *(__half2*)(g_bcH + o)     = __halves2half2(h[0], h[1]);
    *(__half2*)(g_bcH + o + 2) = __halves2half2(h[2], h[3]);
    *(__half2*)(g_bcL + o)     = __halves2half2(l[0], l[1]);
    *(__half2*)(g_bcL + o + 2) = __halves2half2(l[2], l[3]);
}

// VQ argmin + gathers: fp32 quant out + halves into zc cols 1024..1279
__global__ void k_vq(const float* __restrict__ cb,
                     float* __restrict__ quant_out,
                     float* __restrict__ idx_out) {
    int warp = (blockIdx.x * blockDim.x + threadIdx.x) >> 5;
    int lane = threadIdx.x & 31;
    if (warp >= NTOK) return;
    const float* srow = g_scores + (size_t)warp * NCODE;
    float best = 3.0e38f;
    int bi = 0x7fffffff;
    for (int c = lane; c < NCODE; c += 32) {
        float d = g_cbn[c] - 2.f * srow[c];
        if (d < best) { best = d; bi = c; }
    }
#pragma unroll
    for (int o = 16; o; o >>= 1) {
        float ov = __shfl_xor_sync(0xffffffffu, best, o);
        int   oi = __shfl_xor_sync(0xffffffffu, bi, o);
        if (ov < best || (ov == best && oi < bi)) { best = ov; bi = oi; }
    }
    const float4* q = (const float4*)(cb + (size_t)bi * DSYM);
    float4* dst = (float4*)(quant_out + (size_t)warp * DSYM);
#pragma unroll
    for (int i = lane; i < DSYM / 4; i += 32) dst[i] = q[i];
    const float4* qh = (const float4*)(g_cbH + (size_t)bi * DSYM);
    const float4* ql = (const float4*)(g_cbL + (size_t)bi * DSYM);
    float4* dH = (float4*)(g_zcH + (size_t)warp * 1280 + 1024);
    float4* dL = (float4*)(g_zcL + (size_t)warp * 1280 + 1024);
#pragma unroll
    for (int i = lane; i < DSYM / 8; i += 32) { dH[i] = qh[i]; dL[i] = ql[i]; }
    if (lane == 0) idx_out[warp] = (float)bi;
}

__global__ void k_mask(float* __restrict__ mask_out) {
    int t = threadIdx.x;
    if (t < TDIM) mask_out[t] = (g_used[t] == 0) ? 1.f : 0.f;
}

// ---------------- fp16 split tensor GEMM: cp.async + ldmatrix ---------------
// C[M,N] = (Ah+Al)[M,K] @ (Bh+Bl)^T  (B stored [N,K]); D = AhBh + AhBl + AlBh
// CTA 128x128, BK=32, 8 warps (2x4), warp tile 64x32, 2-stage cp.async,
// 64KB smem -> 2 CTAs/SM.
#define STG_B 32768                   // bytes per stage (4 x 8KB)
#define TC_SMEM (2 * STG_B)           // 65536

#define MMA16816(d, a, b)                                             \
    asm volatile(                                                     \
        "mma.sync.aligned.m16n8k16.row.col.f32.f16.f16.f32 "          \
        "{%0,%1,%2,%3},{%4,%5,%6,%7},{%8,%9},{%0,%1,%2,%3};"          \
        : "+f"(d[0]), "+f"(d[1]), "+f"(d[2]), "+f"(d[3])              \
        : "r"(a[0]), "r"(a[1]), "r"(a[2]), "r"(a[3]),                 \
          "r"(b[0]), "r"(b[1]))

static __device__ __forceinline__ uint32_t smem_u32(const void* p) {
    uint32_t a;
    asm("{ .reg .u64 t; cvta.to.shared.u64 t, %1; cvt.u32.u64 %0, t; }"
        : "=r"(a) : "l"(p));
    return a;
}
static __device__ __forceinline__ void cp16(uint32_t dst, const void* src) {
    asm volatile("cp.async.ca.shared.global [%0], [%1], 16;"
                 :: "r"(dst), "l"(src) : "memory");
}
static __device__ __forceinline__ void ldm4(uint32_t& r0, uint32_t& r1,
                                            uint32_t& r2, uint32_t& r3, uint32_t a) {
    asm volatile("ldmatrix.sync.aligned.m8n8.x4.shared.b16 {%0,%1,%2,%3}, [%4];"
                 : "=r"(r0), "=r"(r1), "=r"(r2), "=r"(r3) : "r"(a));
}

__global__ __launch_bounds__(256, 2)
void k_tc(const __half* __restrict__ Ah, const __half* __restrict__ Al, int lda,
          const __half* __restrict__ Bh, const __half* __restrict__ Bl,
          const float* __restrict__ bias, const float* __restrict__ res, int relu,
          float* __restrict__ C, __half* __restrict__ Ch, __half* __restrict__ Cl,
          int ldch, int N, int K)
{
    extern __shared__ char sm[];
    const uint32_t sb = smem_u32(sm);
    const int tid = threadIdx.x;
    const int wid = tid >> 5, lane = tid & 31;
    const int wm = wid & 1, wn = wid >> 1;
    const int g = lane >> 2, t4 = lane & 3;
    const int bm = blockIdx.y * 128, bn = blockIdx.x * 128;

    int cr[2], cc[2];
#pragma unroll
    for (int l = 0; l < 2; l++) {
        int c = tid + l * 256;
        cr[l] = c >> 2;            // row 0..127
        cc[l] = c & 3;             // chunk 0..3
    }

    auto issue_stage = [&](int t) {
        const int kt = t * 32;
        const uint32_t s0 = sb + (t & 1) * STG_B;
#pragma unroll
        for (int l = 0; l < 2; l++) {
            int r = cr[l], ch = cc[l];
            uint32_t d = s0 + r * 64 + ((ch ^ ((r >> 1) & 3)) << 4);
            size_t ga = (size_t)(bm + r) * lda + kt + ch * 8;
            cp16(d,          Ah + ga);
            cp16(d + 8192,   Al + ga);
            size_t gb = (size_t)(bn + r) * K + kt + ch * 8;
            cp16(d + 16384,  Bh + gb);
            cp16(d + 24576,  Bl + gb);
        }
        asm volatile("cp.async.commit_group;" ::: "memory");
    };

    const int amb = (lane & 7) + 8 * ((lane >> 3) & 1);
    const int akl = (lane >> 4) & 1;
    const int swa = (amb >> 1) & 3;
    const int bnb = (lane & 7) + 8 * ((lane >> 4) & 1);
    const int bkl = (lane >> 3) & 1;
    const int swb = (bnb >> 1) & 3;

    float acc[4][4][4] = {};
    const int T = K / 32;

    issue_stage(0);
    issue_stage(1);

    for (int t = 0; t < T; t++) {
        asm volatile("cp.async.wait_group 1;" ::: "memory");
        __syncthreads();

        const uint32_t s0 = sb + (t & 1) * STG_B;
        const uint32_t aH = s0, aL = s0 + 8192;
        const uint32_t bH = s0 + 16384, bL = s0 + 24576;
#pragma unroll
        for (int s = 0; s < 2; s++) {
            uint32_t bh[4][2], bl[4][2];
#pragma unroll
            for (int jp = 0; jp < 2; jp++) {
                uint32_t off = (uint32_t)(wn * 32 + jp * 16 + bnb) * 64
                             + (((s * 2 + bkl) ^ swb) << 4);
                ldm4(bh[2 * jp][0], bh[2 * jp][1], bh[2 * jp + 1][0], bh[2 * jp + 1][1],
                     bH + off);
                ldm4(bl[2 * jp][0], bl[2 * jp][1], bl[2 * jp + 1][0], bl[2 * jp + 1][1],
                     bL + off);
            }
#pragma unroll
            for (int i = 0; i < 4; i++) {
                uint32_t off = (uint32_t)(wm * 64 + i * 16 + amb) * 64
                             + (((s * 2 + akl) ^ swa) << 4);
                uint32_t ah[4], al[4];
                ldm4(ah[0], ah[1], ah[2], ah[3], aH + off);
                ldm4(al[0], al[1], al[2], al[3], aL + off);
#pragma unroll
                for (int j = 0; j < 4; j++) {
                    MMA16816(acc[i][j], ah, bh[j]);
                    MMA16816(acc[i][j], ah, bl[j]);
                    MMA16816(acc[i][j], al, bh[j]);
                }
            }
        }

        if (t + 2 < T) {
            __syncthreads();           // all warps done reading this buffer
            issue_stage(t + 2);
        }
    }

    // ---- epilogue ----
#pragma unroll
    for (int i = 0; i < 4; i++) {
        int row0 = bm + wm * 64 + i * 16 + g;
#pragma unroll
        for (int j = 0; j < 4; j++) {
            int col = bn + wn * 32 + j * 8 + 2 * t4;
            float2 v0 = make_float2(acc[i][j][0], acc[i][j][1]);
            float2 v1 = make_float2(acc[i][j][2], acc[i][j][3]);
            if (bias) {
                float2 bv = *(const float2*)(bias + col);
                v0.x += bv.x; v0.y += bv.y;
                v1.x += bv.x; v1.y += bv.y;
            }
            if (relu) {
                v0.x = fmaxf(v0.x, 0.f); v0.y = fmaxf(v0.y, 0.f);
                v1.x = fmaxf(v1.x, 0.f); v1.y = fmaxf(v1.y, 0.f);
            }
            size_t o0 = (size_t)row0 * N + col;
            size_t o1 = (size_t)(row0 + 8) * N + col;
            if (res) {
                float2 r0 = *(const float2*)(res + o0);
                float2 r1 = *(const float2*)(res + o1);
                v0.x += r0.x; v0.y += r0.y;
                v1.x += r1.x; v1.y += r1.y;
            }
            if (C) {
                *(float2*)(C + o0) = v0;
                *(float2*)(C + o1) = v1;
            }
            if (Ch) {
                __half h0, l0, h1, l1;
                size_t p0 = (size_t)row0 * ldch + col;
                size_t p1 = (size_t)(row0 + 8) * ldch + col;
                split_h(v0.x, h0, l0); split_h(v0.y, h1, l1);
                *(__half2*)(Ch + p0) = __halves2half2(h0, h1);
                *(__half2*)(Cl + p0) = __halves2half2(l0, l1);
                split_h(v1.x, h0, l0); split_h(v1.y, h1, l1);
                *(__half2*)(Ch + p1) = __halves2half2(h0, h1);
                *(__half2*)(Cl + p1) = __halves2half2(l0, l1);
            }
        }
    }
}

// ---------------- launch ----------------------------------------------------
extern "C" void kernel_launch(void* const* d_in, const int* in_sizes, int n_in,
                              void* d_out, int out_size)
{
    const float* token = (const float*)d_in[0];
    const float* syms  = (const float*)d_in[1];
    const float* outs  = (const float*)d_in[3];
    const float* Wq    = (const float*)d_in[5];
    const float* Wread = (const float*)d_in[7];
    const float* bread = (const float*)d_in[8];
    const float* Wsym  = (const float*)d_in[9];
    const float* bsym  = (const float*)d_in[10];
    const float* Wc1   = (const float*)d_in[11];
    const float* bc1   = (const float*)d_in[12];
    const float* Wc2   = (const float*)d_in[13];
    const float* bc2   = (const float*)d_in[14];
    const float* cb    = (const float*)d_in[15];

    float* out        = (float*)d_out;
    float* out_node   = out;
    float* out_quant  = out + (size_t)NTOK * DLAT;
    float* out_idx    = out_quant + (size_t)NTOK * DSYM;
    float* out_mask   = out_idx + NTOK;

#define SYM_PTR(T, sym) ([]{ void* p; cudaGetSymbolAddress(&p, sym); return (T*)p; }())
    float*  scores = SYM_PTR(float,  g_scores);
    __half* bcH = SYM_PTR(__half, g_bcH); __half* bcL = SYM_PTR(__half, g_bcL);
    __half* zcH = SYM_PTR(__half, g_zcH); __half* zcL = SYM_PTR(__half, g_zcL);
    __half* rwH = SYM_PTR(__half, g_rwH); __half* rwL = SYM_PTR(__half, g_rwL);
    __half* hH  = SYM_PTR(__half, g_hH);  __half* hL  = SYM_PTR(__half, g_hL);
    __half* WrH = SYM_PTR(__half, g_WreadH); __half* WrL = SYM_PTR(__half, g_WreadL);
    __half* WsH = SYM_PTR(__half, g_WsymH);  __half* WsL = SYM_PTR(__half, g_WsymL);
    __half* W1H = SYM_PTR(__half, g_Wc1H);   __half* W1L = SYM_PTR(__half, g_Wc1L);
    __half* W2H = SYM_PTR(__half, g_Wc2H);   __half* W2L = SYM_PTR(__half, g_Wc2L);
    __half* cbH = SYM_PTR(__half, g_cbH);    __half* cbL = SYM_PTR(__half, g_cbL);

    static int once = 0;
    if (!once) {
        cudaFuncSetAttribute(k_tc, cudaFuncAttributeMaxDynamicSharedMemorySize, TC_SMEM);
        once = 1;
    }

    k_init_used<<<1, 32>>>();
    k_topidx<<<(NTOK * 32 + 255) / 256, 256>>>(syms, Wq);
    k_cbnorm<<<2, 256>>>(cb);
    { dim3 g(DLAT / 32, 2 * DLAT / 32);        k_cvt_wt<<<g, dim3(32, 8)>>>(Wread, WrH, WrL, 2 * DLAT, DLAT); }
    { dim3 g(DSYM / 32, DLAT / 32);            k_cvt_wt<<<g, dim3(32, 8)>>>(Wsym, WsH, WsL, DLAT, DSYM); }
    { dim3 g(DLAT / 32, (DLAT + DSYM) / 32);   k_cvt_wt<<<g, dim3(32, 8)>>>(Wc1, W1H, W1L, DLAT + DSYM, DLAT); }
    { dim3 g(DLAT / 32, DLAT / 32);            k_cvt_wt<<<g, dim3(32, 8)>>>(Wc2, W2H, W2L, DLAT, DLAT); }
    k_cvt_cb<<<(NCODE * DSYM + 255) / 256, 256>>>(cb);
    k_buscat<<<NTOK * 512 / 256, 256>>>(token, outs);

    // 1) zc[:,0:1024] = bc @ Wread^T + bread   (K=2048, N=1024) -> hi/lo only
    k_tc<<<dim3(DLAT / 128, NTOK / 128), 256, TC_SMEM>>>(
        bcH, bcL, 2 * DLAT, WrH, WrL, bread, nullptr, 0,
        nullptr, zcH, zcL, DLAT + DSYM, DLAT, 2 * DLAT);
    // 2) raw = zc[:,0:1024] @ Wsym^T + bsym    (K=1024, N=256) -> hi/lo
    k_tc<<<dim3(DSYM / 128, NTOK / 128), 256, TC_SMEM>>>(
        zcH, zcL, DLAT + DSYM, WsH, WsL, bsym, nullptr, 0,
        nullptr, rwH, rwL, DSYM, DSYM, DLAT);
    // 3) scores = raw @ cb^T                   (K=256, N=512) -> fp32
    k_tc<<<dim3(NCODE / 128, NTOK / 128), 256, TC_SMEM>>>(
        rwH, rwL, DSYM, cbH, cbL, nullptr, nullptr, 0,
        scores, nullptr, nullptr, 0, NCODE, DSYM);
    k_vq<<<(NTOK * 32 + 255) / 256, 256>>>(cb, out_quant, out_idx);
    // 4) h = relu(zc @ Wc1^T + bc1)            (K=1280, N=1024) -> hi/lo
    k_tc<<<dim3(DLAT / 128, NTOK / 128), 256, TC_SMEM>>>(
        zcH, zcL, DLAT + DSYM, W1H, W1L, bc1, nullptr, 1,
        nullptr, hH, hL, DLAT, DLAT, DLAT + DSYM);
    // 5) out = h @ Wc2^T + bc2 + token         (K=1024, N=1024) -> fp32
    k_tc<<<dim3(DLAT / 128, NTOK / 128), 256, TC_SMEM>>>(
        hH, hL, DLAT, W2H, W2L, bc2, token, 0,
        out_node, nullptr, nullptr, 0, DLAT, DLAT);
    k_mask<<<1, 32>>>(out_mask);
}